// round 1
// baseline (speedup 1.0000x reference)
#include <cuda_runtime.h>

// ---------------------------------------------------------------------------
// NeuronCircuit: compress (MoE-weighted proj) -> causal MHA -> expand
// B=4 S=2048 D=1024 R=512 H=8 NC=NE=8 DH=64, all fp32
//
// Pipeline:
//  1) router_kernel<1024,3>: softmax(x @ w_router_{q,k,v}^T) -> wq,wk,wv [T,8]
//  2) sgemm128 (batched over n): P[t, n*512+r] = x @ compress_neurons  (68.7 GF)
//  3) reduce_qkv: q/k/v[t,r] = sum_n P[t,n,r] * w{q,k,v}[t,n]
//  4) attn_kernel: causal flash attention, fp32, one q-row per thread
//  5) router_kernel<512,1>: wo = softmax(attn @ w_router_o^T)
//  6) build_expand_A: A'[t, n*512+r] = wo[t,n]*attn[t,r]   (reuses P buffer)
//  7) sgemm128: out = A' @ expand_neurons_viewed_[4096,1024] (68.7 GF)
// ---------------------------------------------------------------------------

#define Bz 4
#define Sz 2048
#define Dz 1024
#define Rz 512
#define Hz 8
#define NCz 8
#define DHz 64
#define Tz (Bz * Sz)          // 8192 tokens
#define PCOLS (NCz * Rz)      // 4096

// Scratch (device globals: allocation-free rule)
__device__ float g_P[(size_t)Tz * PCOLS];   // 134 MB, reused as A' for expand
__device__ float g_q[Tz * Rz];
__device__ float g_k[Tz * Rz];
__device__ float g_v[Tz * Rz];
__device__ float g_attn[Tz * Rz];
__device__ float g_wq[Tz * NCz];
__device__ float g_wk[Tz * NCz];
__device__ float g_wv[Tz * NCz];
__device__ float g_wo[Tz * NCz];

// ---------------------------------------------------------------------------
// Router: per-token logits over 8 neurons for up to 3 routers, then softmax.
// One block per token, 8 warps = 8 neurons, warp-reduced dot products.
// ---------------------------------------------------------------------------
template <int DIM, int NR>
__global__ __launch_bounds__(256) void router_kernel(
    const float* __restrict__ x,
    const float* __restrict__ wr0, const float* __restrict__ wr1,
    const float* __restrict__ wr2,
    float* __restrict__ o0, float* __restrict__ o1, float* __restrict__ o2)
{
    __shared__ float xs[DIM];
    __shared__ float lg[NR][8];
    const long t = blockIdx.x;
    const float4* xrow = (const float4*)(x + t * DIM);
    for (int i = threadIdx.x; i < DIM / 4; i += 256)
        ((float4*)xs)[i] = xrow[i];
    __syncthreads();

    const int w = threadIdx.x >> 5;
    const int lane = threadIdx.x & 31;
    const float* wrs[3] = {wr0, wr1, wr2};
#pragma unroll
    for (int rt = 0; rt < NR; rt++) {
        const float4* wv4 = (const float4*)(wrs[rt] + w * DIM);
        float s = 0.f;
#pragma unroll
        for (int i = lane; i < DIM / 4; i += 32) {
            float4 a = ((const float4*)xs)[i];
            float4 b = wv4[i];
            s += a.x * b.x + a.y * b.y + a.z * b.z + a.w * b.w;
        }
#pragma unroll
        for (int off = 16; off; off >>= 1)
            s += __shfl_xor_sync(0xffffffffu, s, off);
        if (lane == 0) lg[rt][w] = s;
    }
    __syncthreads();

    if (threadIdx.x < NR) {
        const int rt = threadIdx.x;
        float mx = lg[rt][0];
#pragma unroll
        for (int n = 1; n < 8; n++) mx = fmaxf(mx, lg[rt][n]);
        float e[8];
        float sum = 0.f;
#pragma unroll
        for (int n = 0; n < 8; n++) { e[n] = __expf(lg[rt][n] - mx); sum += e[n]; }
        const float inv = 1.f / sum;
        float* o = (rt == 0 ? o0 : (rt == 1 ? o1 : o2)) + t * 8;
#pragma unroll
        for (int n = 0; n < 8; n++) o[n] = e[n] * inv;
    }
}

// ---------------------------------------------------------------------------
// Classic 128x128x8 fp32 SGEMM, row-major, batched via blockIdx.z.
// All dims here are multiples of the tile sizes (no bounds checks needed).
// ---------------------------------------------------------------------------
__global__ __launch_bounds__(256) void sgemm128(
    const float* __restrict__ A, const float* __restrict__ B,
    float* __restrict__ C, int K, int lda, int ldb, int ldc,
    long strideB, long strideC)
{
    const int BK = 8;
    __shared__ float As[BK][128];
    __shared__ float Bs[BK][128];

    B += (long)blockIdx.z * strideB;
    C += (long)blockIdx.z * strideC;

    const int brow = blockIdx.y * 128;
    const int bcol = blockIdx.x * 128;
    const int tid = threadIdx.x;

    const int arow = tid >> 1;             // 0..127
    const int acol = (tid & 1) << 2;       // 0 or 4
    const int brl = tid >> 5;              // 0..7
    const int bcl = (tid & 31) << 2;       // 0..124
    const int tx = tid & 15;
    const int ty = tid >> 4;

    float acc[8][8];
#pragma unroll
    for (int i = 0; i < 8; i++)
#pragma unroll
        for (int j = 0; j < 8; j++) acc[i][j] = 0.f;

    const float* Aptr = A + (long)(brow + arow) * lda + acol;
    const float* Bptr = B + (long)brl * ldb + bcol + bcl;

    for (int k0 = 0; k0 < K; k0 += BK) {
        float4 av = *(const float4*)(Aptr + k0);
        As[acol + 0][arow] = av.x;
        As[acol + 1][arow] = av.y;
        As[acol + 2][arow] = av.z;
        As[acol + 3][arow] = av.w;
        *(float4*)&Bs[brl][bcl] = *(const float4*)(Bptr + (long)k0 * ldb);
        __syncthreads();

#pragma unroll
        for (int k = 0; k < BK; k++) {
            float af[8], bf[8];
            float4 a0 = *(const float4*)&As[k][ty * 8];
            float4 a1 = *(const float4*)&As[k][ty * 8 + 4];
            float4 b0 = *(const float4*)&Bs[k][tx * 8];
            float4 b1 = *(const float4*)&Bs[k][tx * 8 + 4];
            af[0] = a0.x; af[1] = a0.y; af[2] = a0.z; af[3] = a0.w;
            af[4] = a1.x; af[5] = a1.y; af[6] = a1.z; af[7] = a1.w;
            bf[0] = b0.x; bf[1] = b0.y; bf[2] = b0.z; bf[3] = b0.w;
            bf[4] = b1.x; bf[5] = b1.y; bf[6] = b1.z; bf[7] = b1.w;
#pragma unroll
            for (int i = 0; i < 8; i++)
#pragma unroll
                for (int j = 0; j < 8; j++) acc[i][j] += af[i] * bf[j];
        }
        __syncthreads();
    }

#pragma unroll
    for (int i = 0; i < 8; i++) {
        float* Cp = C + (long)(brow + ty * 8 + i) * ldc + bcol + tx * 8;
        float4 c0 = make_float4(acc[i][0], acc[i][1], acc[i][2], acc[i][3]);
        float4 c1 = make_float4(acc[i][4], acc[i][5], acc[i][6], acc[i][7]);
        *(float4*)Cp = c0;
        *(float4*)(Cp + 4) = c1;
    }
}

// ---------------------------------------------------------------------------
// q/k/v[t,r] = sum_n P[t, n*512 + r] * w{q,k,v}[t,n]
// ---------------------------------------------------------------------------
__global__ __launch_bounds__(128) void reduce_qkv(
    const float* __restrict__ P,
    const float* __restrict__ wq, const float* __restrict__ wk,
    const float* __restrict__ wv,
    float* __restrict__ q, float* __restrict__ k, float* __restrict__ v)
{
    const long t = blockIdx.x;
    __shared__ float sq[8], sk[8], sv[8];
    if (threadIdx.x < 8) {
        sq[threadIdx.x] = wq[t * 8 + threadIdx.x];
        sk[threadIdx.x] = wk[t * 8 + threadIdx.x];
        sv[threadIdx.x] = wv[t * 8 + threadIdx.x];
    }
    __syncthreads();
    const float* Pt = P + t * PCOLS;
    for (int r = threadIdx.x; r < Rz; r += 128) {
        float aq = 0.f, ak = 0.f, av = 0.f;
#pragma unroll
        for (int n = 0; n < 8; n++) {
            float p = Pt[n * Rz + r];
            aq += p * sq[n];
            ak += p * sk[n];
            av += p * sv[n];
        }
        q[t * Rz + r] = aq;
        k[t * Rz + r] = ak;
        v[t * Rz + r] = av;
    }
}

// ---------------------------------------------------------------------------
// Causal flash attention, fp32. Grid (S/128, B*H); one q-row per thread.
// q and accumulator register-resident; K/V tiles (32 x 64) in smem.
// Scores buffered per tile so softmax rescale is amortized (1 per 32 kv).
// ---------------------------------------------------------------------------
__global__ __launch_bounds__(128) void attn_kernel(
    const float* __restrict__ q, const float* __restrict__ k,
    const float* __restrict__ v, float* __restrict__ out)
{
    const int KV = 32;
    __shared__ float Ks[KV][DHz];
    __shared__ float Vs[KV][DHz];

    const int bh = blockIdx.y;
    const int b = bh >> 3;
    const int h = bh & 7;
    const int qrow = blockIdx.x * 128 + threadIdx.x;

    const float* qp = q + ((long)b * Sz + qrow) * Rz + h * DHz;
    float qreg[DHz];
#pragma unroll
    for (int d = 0; d < DHz; d++) qreg[d] = qp[d];

    float acc[DHz];
#pragma unroll
    for (int d = 0; d < DHz; d++) acc[d] = 0.f;
    float m = -1e30f, l = 0.f;

    const float* kb = k + (long)b * Sz * Rz + h * DHz;
    const float* vb = v + (long)b * Sz * Rz + h * DHz;
    const int ntiles = (blockIdx.x * 128 + 127) / KV + 1;

    for (int tt = 0; tt < ntiles; tt++) {
        const int base = tt * KV;
        // cooperative K/V tile load (KV*DHz/4 = 512 float4s / 128 threads)
        for (int i = threadIdx.x; i < KV * DHz / 4; i += 128) {
            int row = i >> 4;
            int col = (i & 15) << 2;
            *(float4*)&Ks[row][col] = *(const float4*)(kb + (long)(base + row) * Rz + col);
            *(float4*)&Vs[row][col] = *(const float4*)(vb + (long)(base + row) * Rz + col);
        }
        __syncthreads();

        if (base <= qrow) {
            float sc[KV];
            float tmax = -1e30f;
#pragma unroll
            for (int j = 0; j < KV; j++) {
                float s = 0.f;
#pragma unroll
                for (int d = 0; d < DHz; d++) s += qreg[d] * Ks[j][d];
                s *= 0.125f;                          // 1/sqrt(64)
                s = (base + j <= qrow) ? s : -1e30f;  // causal
                sc[j] = s;
                tmax = fmaxf(tmax, s);
            }
            const float mn = fmaxf(m, tmax);
            const float corr = __expf(m - mn);
            l *= corr;
#pragma unroll
            for (int d = 0; d < DHz; d++) acc[d] *= corr;
#pragma unroll
            for (int j = 0; j < KV; j++) {
                float p = __expf(sc[j] - mn);
                l += p;
#pragma unroll
                for (int d = 0; d < DHz; d++) acc[d] += p * Vs[j][d];
            }
            m = mn;
        }
        __syncthreads();
    }

    const float inv = 1.f / l;
    float* op = out + ((long)b * Sz + qrow) * Rz + h * DHz;
#pragma unroll
    for (int d = 0; d < DHz; d++) op[d] = acc[d] * inv;
}

// ---------------------------------------------------------------------------
// A'[t, n*512 + r] = wo[t,n] * attn[t,r]
// ---------------------------------------------------------------------------
__global__ __launch_bounds__(256) void build_expand_A(
    const float* __restrict__ attn, const float* __restrict__ wo,
    float* __restrict__ Aout)
{
    __shared__ float as_[Rz];
    __shared__ float ws[8];
    const long t = blockIdx.x;
    for (int i = threadIdx.x; i < Rz / 4; i += 256)
        ((float4*)as_)[i] = ((const float4*)(attn + t * Rz))[i];
    if (threadIdx.x < 8) ws[threadIdx.x] = wo[t * 8 + threadIdx.x];
    __syncthreads();
    for (int i = threadIdx.x; i < (8 * Rz / 4); i += 256) {
        int n = i >> 7;
        int r4 = i & 127;
        float4 a = ((float4*)as_)[r4];
        float wn = ws[n];
        float4 o = make_float4(a.x * wn, a.y * wn, a.z * wn, a.w * wn);
        ((float4*)(Aout + t * PCOLS + n * Rz))[r4] = o;
    }
}

// ---------------------------------------------------------------------------
extern "C" void kernel_launch(void* const* d_in, const int* in_sizes, int n_in,
                              void* d_out, int out_size)
{
    const float* x   = (const float*)d_in[0];
    // d_in[1] = mask: always causal tril -> applied analytically, not read
    const float* CN  = (const float*)d_in[2];  // [NC, D, R]
    const float* EN  = (const float*)d_in[3];  // [NE, R, D] == [4096,1024] row-major
    const float* wrq = (const float*)d_in[4];
    const float* wrk = (const float*)d_in[5];
    const float* wrv = (const float*)d_in[6];
    const float* wro = (const float*)d_in[7];
    float* out = (float*)d_out;

    float *P, *q, *k, *v, *attn, *wq, *wk, *wv, *wo;
    cudaGetSymbolAddress((void**)&P,    g_P);
    cudaGetSymbolAddress((void**)&q,    g_q);
    cudaGetSymbolAddress((void**)&k,    g_k);
    cudaGetSymbolAddress((void**)&v,    g_v);
    cudaGetSymbolAddress((void**)&attn, g_attn);
    cudaGetSymbolAddress((void**)&wq,   g_wq);
    cudaGetSymbolAddress((void**)&wk,   g_wk);
    cudaGetSymbolAddress((void**)&wv,   g_wv);
    cudaGetSymbolAddress((void**)&wo,   g_wo);

    // 1) compress routers (q,k,v share one pass over x)
    router_kernel<Dz, 3><<<Tz, 256>>>(x, wrq, wrk, wrv, wq, wk, wv);

    // 2) P = x @ compress_neurons  (batched over NC=8)
    sgemm128<<<dim3(Rz / 128, Tz / 128, NCz), 256>>>(
        x, CN, P, Dz, Dz, Rz, PCOLS, (long)Dz * Rz, (long)Rz);

    // 3) weighted reduce -> q,k,v
    reduce_qkv<<<Tz, 128>>>(P, wq, wk, wv, q, k, v);

    // 4) causal attention
    attn_kernel<<<dim3(Sz / 128, Bz * Hz), 128>>>(q, k, v, attn);

    // 5) expand router
    router_kernel<Rz, 1><<<Tz, 256>>>(attn, wro, nullptr, nullptr,
                                      wo, nullptr, nullptr);

    // 6) A' = wo (x) attn   (reuses P)
    build_expand_A<<<Tz, 256>>>(attn, wo, P);

    // 7) out = A' @ expand_neurons
    sgemm128<<<dim3(Dz / 128, Tz / 128, 1), 256>>>(
        P, EN, out, PCOLS, PCOLS, Dz, Dz, 0, 0);
}

// round 3
// speedup vs baseline: 1.1359x; 1.1359x over previous
#include <cuda_runtime.h>
#include <cstdint>

// ---------------------------------------------------------------------------
// NeuronCircuit: compress (MoE-weighted proj) -> causal MHA -> expand
// B=4 S=2048 D=1024 R=512 H=8 NC=NE=8 DH=64
//
// Round 2 -> 3: harness compiles via compute_103 (non-'a') PTX, so tcgen05/
// TMA are unavailable. GEMMs use baseline-PTX mma.sync.m16n8k8 tf32 (legacy
// HMMA path) with cp.async double-buffered SW128-swizzled smem tiles.
// ---------------------------------------------------------------------------

#define Bz 4
#define Sz 2048
#define Dz 1024
#define Rz 512
#define Hz 8
#define NCz 8
#define DHz 64
#define Tz (Bz * Sz)          // 8192 tokens
#define PCOLS (NCz * Rz)      // 4096

// Scratch (device globals: allocation-free rule)
__device__ float g_P[(size_t)Tz * PCOLS];   // 134 MB, reused as A' for expand
__device__ float g_q[Tz * Rz];
__device__ float g_k[Tz * Rz];
__device__ float g_v[Tz * Rz];
__device__ float g_attn[Tz * Rz];
__device__ float g_wq[Tz * NCz];
__device__ float g_wk[Tz * NCz];
__device__ float g_wv[Tz * NCz];
__device__ float g_wo[Tz * NCz];
__device__ float g_CNt[(size_t)NCz * Rz * Dz];   // [NC][R][D]  (16 MB)
__device__ float g_ENt[(size_t)Dz * PCOLS];      // [D][NE*R]   (16 MB)

// ---------------------------------------------------------------------------
// Baseline-PTX helpers (valid on compute_103): cp.async + mma.sync tf32
// ---------------------------------------------------------------------------
#define SW128(off) ((off) ^ (((off) >> 3) & 0x70))

__device__ __forceinline__ void cp_async16(void* smem_dst, const void* gmem_src) {
    uint32_t d = (uint32_t)__cvta_generic_to_shared(smem_dst);
    asm volatile("cp.async.cg.shared.global [%0], [%1], 16;"
                 :: "r"(d), "l"(gmem_src) : "memory");
}
#define CP_COMMIT() asm volatile("cp.async.commit_group;" ::: "memory")
#define CP_WAIT(n)  asm volatile("cp.async.wait_group %0;" :: "n"(n) : "memory")

__device__ __forceinline__ uint32_t ld_tf32(const char* base, int row, int colByte) {
    uint32_t off = SW128((uint32_t)((row << 7) + colByte));
    uint32_t v = *(const uint32_t*)(base + off);
    uint32_t r;
    asm("cvt.rna.tf32.f32 %0, %1;" : "=r"(r) : "f"(__uint_as_float(v)));
    return r;
}

__device__ __forceinline__ void mma_tf32(float* d, const uint32_t* a, const uint32_t* b) {
    asm volatile(
        "mma.sync.aligned.m16n8k8.row.col.f32.tf32.tf32.f32 "
        "{%0,%1,%2,%3}, {%4,%5,%6,%7}, {%8,%9}, {%0,%1,%2,%3};"
        : "+f"(d[0]), "+f"(d[1]), "+f"(d[2]), "+f"(d[3])
        : "r"(a[0]), "r"(a[1]), "r"(a[2]), "r"(a[3]), "r"(b[0]), "r"(b[1]));
}

// ---------------------------------------------------------------------------
// Weight transpose: out[cols][rows] = in[rows][cols], batched over z.
// ---------------------------------------------------------------------------
__global__ __launch_bounds__(256) void transpose_kernel(
    const float* __restrict__ in, float* __restrict__ out,
    int rows, int cols, long zStride)
{
    __shared__ float tile[32][33];
    in  += (long)blockIdx.z * zStride;
    out += (long)blockIdx.z * zStride;
    const int c0 = blockIdx.x * 32;
    const int r0 = blockIdx.y * 32;
    const int tx = threadIdx.x & 31;
    const int ty = threadIdx.x >> 5;          // 0..7
#pragma unroll
    for (int j = 0; j < 32; j += 8)
        tile[ty + j][tx] = in[(long)(r0 + ty + j) * cols + c0 + tx];
    __syncthreads();
#pragma unroll
    for (int j = 0; j < 32; j += 8)
        out[(long)(c0 + ty + j) * rows + r0 + tx] = tile[tx][ty + j];
}

// ---------------------------------------------------------------------------
// tf32 mma.sync GEMM: C[M,N] = A[M,K] (row-major) x Bt[N,K] (K-major rows)
// CTA tile 128x128, BK=32, 8 warps (warp tile 64x32), 2-stage cp.async.
// SMEM: stage s at tiles + s*32768 (A 16KB then B 16KB), SW128-swizzled
// rows of 32 floats (=128B).
// ---------------------------------------------------------------------------
#define GEMM_SMEM_TOTAL (2 * 32768)

__global__ __launch_bounds__(256) void tf32_gemm(
    const float* __restrict__ A, const float* __restrict__ Bt,
    float* __restrict__ C, int K, int lda, int ldb, int ldc,
    long bStride, long cStride)
{
    extern __shared__ __align__(1024) char smem[];
    const int tid = threadIdx.x;
    const int wid = tid >> 5;
    const int lane = tid & 31;
    const int g = lane >> 2;        // group (row within fragment)
    const int t = lane & 3;         // thread-in-group (k within fragment)
    const int warp_m = wid >> 2;    // 0..1
    const int warp_n = wid & 3;     // 0..3

    Bt += (long)blockIdx.z * bStride;
    C  += (long)blockIdx.z * cStride;
    const int brow = blockIdx.y * 128;
    const int bcol = blockIdx.x * 128;

    const float* Ab = A + (long)brow * lda;
    const float* Bb = Bt + (long)bcol * ldb;

    // loader: 128 rows x 32 floats per matrix = 1024 16B chunks each
    const int lrow = tid >> 1;             // 0..127 (2 threads per row)
    const int lch4 = (tid & 1) << 2;       // chunk 0..3 or 4..7 start
    auto load_chunk = [&](int k0, int s) {
        char* sA = smem + s * 32768;
        char* sB = sA + 16384;
        const float* ga = Ab + (long)lrow * lda + k0 + (lch4 << 2);
        const float* gb = Bb + (long)lrow * ldb + k0 + (lch4 << 2);
#pragma unroll
        for (int c = 0; c < 4; c++) {
            const uint32_t off = SW128((uint32_t)((lrow << 7) + ((lch4 + c) << 4)));
            cp_async16(sA + off, ga + (c << 2));
            cp_async16(sB + off, gb + (c << 2));
        }
    };

    float acc[4][4][4];
#pragma unroll
    for (int i = 0; i < 4; i++)
#pragma unroll
        for (int j = 0; j < 4; j++)
#pragma unroll
            for (int r = 0; r < 4; r++) acc[i][j][r] = 0.f;

    const int NCH = K >> 5;
    load_chunk(0, 0);
    CP_COMMIT();

    for (int i = 0; i < NCH; i++) {
        if (i + 1 < NCH) {
            load_chunk((i + 1) << 5, (i + 1) & 1);
            CP_COMMIT();
            CP_WAIT(1);
        } else {
            CP_WAIT(0);
        }
        __syncthreads();

        const char* sA = smem + (i & 1) * 32768;
        const char* sB = sA + 16384;
#pragma unroll
        for (int ks = 0; ks < 4; ks++) {
            const int c0 = ((ks << 3) + t) << 2;   // byte col of k0+t
            const int c1 = c0 + 16;                // byte col of k0+t+4
            uint32_t bf[4][2];
#pragma unroll
            for (int nt = 0; nt < 4; nt++) {
                const int cb = warp_n * 32 + nt * 8 + g;
                bf[nt][0] = ld_tf32(sB, cb, c0);
                bf[nt][1] = ld_tf32(sB, cb, c1);
            }
#pragma unroll
            for (int mt = 0; mt < 4; mt++) {
                const int rb = warp_m * 64 + mt * 16 + g;
                uint32_t af[4];
                af[0] = ld_tf32(sA, rb,     c0);
                af[1] = ld_tf32(sA, rb + 8, c0);
                af[2] = ld_tf32(sA, rb,     c1);
                af[3] = ld_tf32(sA, rb + 8, c1);
#pragma unroll
                for (int nt = 0; nt < 4; nt++)
                    mma_tf32(acc[mt][nt], af, bf[nt]);
            }
        }
        __syncthreads();
    }

    // epilogue: c0,c1 at (row, col+2t), c2,c3 at (row+8, col+2t)
#pragma unroll
    for (int mt = 0; mt < 4; mt++) {
        const int row = brow + warp_m * 64 + mt * 16 + g;
#pragma unroll
        for (int nt = 0; nt < 4; nt++) {
            const int col = bcol + warp_n * 32 + nt * 8 + 2 * t;
            float* Cp = C + (long)row * ldc + col;
            *(float2*)Cp = make_float2(acc[mt][nt][0], acc[mt][nt][1]);
            *(float2*)(Cp + 8 * ldc) = make_float2(acc[mt][nt][2], acc[mt][nt][3]);
        }
    }
}

// ---------------------------------------------------------------------------
// Router: per-token logits over 8 neurons for up to 3 routers, then softmax.
// ---------------------------------------------------------------------------
template <int DIM, int NR>
__global__ __launch_bounds__(256) void router_kernel(
    const float* __restrict__ x,
    const float* __restrict__ wr0, const float* __restrict__ wr1,
    const float* __restrict__ wr2,
    float* __restrict__ o0, float* __restrict__ o1, float* __restrict__ o2)
{
    __shared__ float xs[DIM];
    __shared__ float lg[NR][8];
    const long t = blockIdx.x;
    const float4* xrow = (const float4*)(x + t * DIM);
    for (int i = threadIdx.x; i < DIM / 4; i += 256)
        ((float4*)xs)[i] = xrow[i];
    __syncthreads();

    const int w = threadIdx.x >> 5;
    const int lane = threadIdx.x & 31;
    const float* wrs[3] = {wr0, wr1, wr2};
#pragma unroll
    for (int rt = 0; rt < NR; rt++) {
        const float4* wv4 = (const float4*)(wrs[rt] + w * DIM);
        float s = 0.f;
#pragma unroll
        for (int i = lane; i < DIM / 4; i += 32) {
            float4 a = ((const float4*)xs)[i];
            float4 b = wv4[i];
            s += a.x * b.x + a.y * b.y + a.z * b.z + a.w * b.w;
        }
#pragma unroll
        for (int off = 16; off; off >>= 1)
            s += __shfl_xor_sync(0xffffffffu, s, off);
        if (lane == 0) lg[rt][w] = s;
    }
    __syncthreads();

    if (threadIdx.x < NR) {
        const int rt = threadIdx.x;
        float mx = lg[rt][0];
#pragma unroll
        for (int n = 1; n < 8; n++) mx = fmaxf(mx, lg[rt][n]);
        float e[8];
        float sum = 0.f;
#pragma unroll
        for (int n = 0; n < 8; n++) { e[n] = __expf(lg[rt][n] - mx); sum += e[n]; }
        const float inv = 1.f / sum;
        float* o = (rt == 0 ? o0 : (rt == 1 ? o1 : o2)) + t * 8;
#pragma unroll
        for (int n = 0; n < 8; n++) o[n] = e[n] * inv;
    }
}

// ---------------------------------------------------------------------------
// q/k/v[t,r] = sum_n P[t, n*512 + r] * w{q,k,v}[t,n]
// ---------------------------------------------------------------------------
__global__ __launch_bounds__(128) void reduce_qkv(
    const float* __restrict__ P,
    const float* __restrict__ wq, const float* __restrict__ wk,
    const float* __restrict__ wv,
    float* __restrict__ q, float* __restrict__ k, float* __restrict__ v)
{
    const long t = blockIdx.x;
    __shared__ float sq[8], sk[8], sv[8];
    if (threadIdx.x < 8) {
        sq[threadIdx.x] = wq[t * 8 + threadIdx.x];
        sk[threadIdx.x] = wk[t * 8 + threadIdx.x];
        sv[threadIdx.x] = wv[t * 8 + threadIdx.x];
    }
    __syncthreads();
    const float* Pt = P + t * PCOLS;
    for (int r = threadIdx.x; r < Rz; r += 128) {
        float aq = 0.f, ak = 0.f, av = 0.f;
#pragma unroll
        for (int n = 0; n < 8; n++) {
            float p = Pt[n * Rz + r];
            aq += p * sq[n];
            ak += p * sk[n];
            av += p * sv[n];
        }
        q[t * Rz + r] = aq;
        k[t * Rz + r] = ak;
        v[t * Rz + r] = av;
    }
}

// ---------------------------------------------------------------------------
// Causal flash attention, fp32 (unchanged this round).
// ---------------------------------------------------------------------------
__global__ __launch_bounds__(128) void attn_kernel(
    const float* __restrict__ q, const float* __restrict__ k,
    const float* __restrict__ v, float* __restrict__ out)
{
    const int KV = 32;
    __shared__ float Ks[KV][DHz];
    __shared__ float Vs[KV][DHz];

    const int bh = blockIdx.y;
    const int b = bh >> 3;
    const int h = bh & 7;
    const int qrow = blockIdx.x * 128 + threadIdx.x;

    const float* qp = q + ((long)b * Sz + qrow) * Rz + h * DHz;
    float qreg[DHz];
#pragma unroll
    for (int d = 0; d < DHz; d++) qreg[d] = qp[d];

    float acc[DHz];
#pragma unroll
    for (int d = 0; d < DHz; d++) acc[d] = 0.f;
    float m = -1e30f, l = 0.f;

    const float* kb = k + (long)b * Sz * Rz + h * DHz;
    const float* vb = v + (long)b * Sz * Rz + h * DHz;
    const int ntiles = (blockIdx.x * 128 + 127) / KV + 1;

    for (int tt = 0; tt < ntiles; tt++) {
        const int base = tt * KV;
        for (int i = threadIdx.x; i < KV * DHz / 4; i += 128) {
            int row = i >> 4;
            int col = (i & 15) << 2;
            *(float4*)&Ks[row][col] = *(const float4*)(kb + (long)(base + row) * Rz + col);
            *(float4*)&Vs[row][col] = *(const float4*)(vb + (long)(base + row) * Rz + col);
        }
        __syncthreads();

        if (base <= qrow) {
            float sc[KV];
            float tmax = -1e30f;
#pragma unroll
            for (int j = 0; j < KV; j++) {
                float s = 0.f;
#pragma unroll
                for (int d = 0; d < DHz; d++) s += qreg[d] * Ks[j][d];
                s *= 0.125f;
                s = (base + j <= qrow) ? s : -1e30f;
                sc[j] = s;
                tmax = fmaxf(tmax, s);
            }
            const float mn = fmaxf(m, tmax);
            const float corr = __expf(m - mn);
            l *= corr;
#pragma unroll
            for (int d = 0; d < DHz; d++) acc[d] *= corr;
#pragma unroll
            for (int j = 0; j < KV; j++) {
                float p = __expf(sc[j] - mn);
                l += p;
#pragma unroll
                for (int d = 0; d < DHz; d++) acc[d] += p * Vs[j][d];
            }
            m = mn;
        }
        __syncthreads();
    }

    const float inv = 1.f / l;
    float* op = out + ((long)b * Sz + qrow) * Rz + h * DHz;
#pragma unroll
    for (int d = 0; d < DHz; d++) op[d] = acc[d] * inv;
}

// ---------------------------------------------------------------------------
// A'[t, n*512 + r] = wo[t,n] * attn[t,r]
// ---------------------------------------------------------------------------
__global__ __launch_bounds__(256) void build_expand_A(
    const float* __restrict__ attn, const float* __restrict__ wo,
    float* __restrict__ Aout)
{
    __shared__ float as_[Rz];
    __shared__ float ws[8];
    const long t = blockIdx.x;
    for (int i = threadIdx.x; i < Rz / 4; i += 256)
        ((float4*)as_)[i] = ((const float4*)(attn + t * Rz))[i];
    if (threadIdx.x < 8) ws[threadIdx.x] = wo[t * 8 + threadIdx.x];
    __syncthreads();
    for (int i = threadIdx.x; i < (8 * Rz / 4); i += 256) {
        int n = i >> 7;
        int r4 = i & 127;
        float4 a = ((float4*)as_)[r4];
        float wn = ws[n];
        ((float4*)(Aout + t * PCOLS + n * Rz))[r4] =
            make_float4(a.x * wn, a.y * wn, a.z * wn, a.w * wn);
    }
}

// ---------------------------------------------------------------------------
extern "C" void kernel_launch(void* const* d_in, const int* in_sizes, int n_in,
                              void* d_out, int out_size)
{
    const float* x   = (const float*)d_in[0];
    // d_in[1] = mask: always causal tril -> applied analytically, not read
    const float* CN  = (const float*)d_in[2];  // [NC, D, R]
    const float* EN  = (const float*)d_in[3];  // [NE, R, D]
    const float* wrq = (const float*)d_in[4];
    const float* wrk = (const float*)d_in[5];
    const float* wrv = (const float*)d_in[6];
    const float* wro = (const float*)d_in[7];
    float* out = (float*)d_out;

    float *P, *q, *k, *v, *attn, *wq, *wk, *wv, *wo, *CNt, *ENt;
    cudaGetSymbolAddress((void**)&P,    g_P);
    cudaGetSymbolAddress((void**)&q,    g_q);
    cudaGetSymbolAddress((void**)&k,    g_k);
    cudaGetSymbolAddress((void**)&v,    g_v);
    cudaGetSymbolAddress((void**)&attn, g_attn);
    cudaGetSymbolAddress((void**)&wq,   g_wq);
    cudaGetSymbolAddress((void**)&wk,   g_wk);
    cudaGetSymbolAddress((void**)&wv,   g_wv);
    cudaGetSymbolAddress((void**)&wo,   g_wo);
    cudaGetSymbolAddress((void**)&CNt,  g_CNt);
    cudaGetSymbolAddress((void**)&ENt,  g_ENt);

    cudaFuncSetAttribute(tf32_gemm, cudaFuncAttributeMaxDynamicSharedMemorySize,
                         GEMM_SMEM_TOTAL);

    // 0) transpose weights to K-major for the B operand
    transpose_kernel<<<dim3(Rz / 32, Dz / 32, NCz), 256>>>(
        CN, CNt, Dz, Rz, (long)Dz * Rz);
    transpose_kernel<<<dim3(Dz / 32, PCOLS / 32, 1), 256>>>(
        EN, ENt, PCOLS, Dz, 0);

    // 1) compress routers (q,k,v share one pass over x)
    router_kernel<Dz, 3><<<Tz, 256>>>(x, wrq, wrk, wrv, wq, wk, wv);

    // 2) P = x @ compress_neurons  (mma.sync tf32, batched over NC=8)
    tf32_gemm<<<dim3(Rz / 128, Tz / 128, NCz), 256, GEMM_SMEM_TOTAL>>>(
        x, CNt, P, Dz, Dz, Dz, PCOLS, (long)Rz * Dz, (long)Rz);

    // 3) weighted reduce -> q,k,v
    reduce_qkv<<<Tz, 128>>>(P, wq, wk, wv, q, k, v);

    // 4) causal attention
    attn_kernel<<<dim3(Sz / 128, Bz * Hz), 128>>>(q, k, v, attn);

    // 5) expand router
    router_kernel<Rz, 1><<<Tz, 256>>>(attn, wro, nullptr, nullptr,
                                      wo, nullptr, nullptr);

    // 6) A' = wo (x) attn   (reuses P)
    build_expand_A<<<Tz, 256>>>(attn, wo, P);

    // 7) out = A' @ expand_neurons  (mma.sync tf32)
    tf32_gemm<<<dim3(Dz / 128, Tz / 128, 1), 256, GEMM_SMEM_TOTAL>>>(
        P, ENt, out, PCOLS, PCOLS, PCOLS, Dz, 0, 0);
}

// round 4
// speedup vs baseline: 1.2051x; 1.0609x over previous
#include <cuda_runtime.h>
#include <cstdint>

// ---------------------------------------------------------------------------
// NeuronCircuit: compress (MoE-weighted proj) -> causal MHA -> expand
// B=4 S=2048 D=1024 R=512 H=8 NC=NE=8 DH=64
//
// Round 3 -> 4:
//  * attention: float4 smem reads (was scalar broadcast LDS -> crossbar bound)
//  * gemm: tf32 rounding hoisted to data-at-rest (round_tf32 / transpose /
//    build_expand_A emit pre-rounded fp32); inner loop feeds raw regs to HMMA
//  * gemm: register double-buffered fragments (LDS for ks+1 overlaps MMA ks)
// ---------------------------------------------------------------------------

#define Bz 4
#define Sz 2048
#define Dz 1024
#define Rz 512
#define Hz 8
#define NCz 8
#define DHz 64
#define Tz (Bz * Sz)          // 8192 tokens
#define PCOLS (NCz * Rz)      // 4096

// Scratch (device globals: allocation-free rule)
__device__ float g_P[(size_t)Tz * PCOLS];   // 134 MB, reused as A' for expand
__device__ float g_Xr[(size_t)Tz * Dz];     // tf32-rounded x (32 MB)
__device__ float g_q[Tz * Rz];
__device__ float g_k[Tz * Rz];
__device__ float g_v[Tz * Rz];
__device__ float g_attn[Tz * Rz];
__device__ float g_wq[Tz * NCz];
__device__ float g_wk[Tz * NCz];
__device__ float g_wv[Tz * NCz];
__device__ float g_wo[Tz * NCz];
__device__ float g_CNt[(size_t)NCz * Rz * Dz];   // [NC][R][D]  (16 MB)
__device__ float g_ENt[(size_t)Dz * PCOLS];      // [D][NE*R]   (16 MB)

// ---------------------------------------------------------------------------
// Baseline-PTX helpers (valid on compute_103): cp.async + mma.sync tf32
// ---------------------------------------------------------------------------
#define SW128(off) ((off) ^ (((off) >> 3) & 0x70))

__device__ __forceinline__ void cp_async16(void* smem_dst, const void* gmem_src) {
    uint32_t d = (uint32_t)__cvta_generic_to_shared(smem_dst);
    asm volatile("cp.async.cg.shared.global [%0], [%1], 16;"
                 :: "r"(d), "l"(gmem_src) : "memory");
}
#define CP_COMMIT() asm volatile("cp.async.commit_group;" ::: "memory")
#define CP_WAIT(n)  asm volatile("cp.async.wait_group %0;" :: "n"(n) : "memory")

__device__ __forceinline__ float tf32r(float x) {
    uint32_t r;
    asm("cvt.rna.tf32.f32 %0, %1;" : "=r"(r) : "f"(x));
    return __uint_as_float(r);
}

__device__ __forceinline__ void mma_tf32(float* d, const uint32_t* a, const uint32_t* b) {
    asm volatile(
        "mma.sync.aligned.m16n8k8.row.col.f32.tf32.tf32.f32 "
        "{%0,%1,%2,%3}, {%4,%5,%6,%7}, {%8,%9}, {%0,%1,%2,%3};"
        : "+f"(d[0]), "+f"(d[1]), "+f"(d[2]), "+f"(d[3])
        : "r"(a[0]), "r"(a[1]), "r"(a[2]), "r"(a[3]), "r"(b[0]), "r"(b[1]));
}

// ---------------------------------------------------------------------------
// Elementwise tf32 rounding (grid-stride, float4)
// ---------------------------------------------------------------------------
__global__ __launch_bounds__(256) void round_tf32(
    const float* __restrict__ in, float* __restrict__ out, long n4)
{
    for (long i = blockIdx.x * 256L + threadIdx.x; i < n4; i += gridDim.x * 256L) {
        float4 v = ((const float4*)in)[i];
        v.x = tf32r(v.x); v.y = tf32r(v.y); v.z = tf32r(v.z); v.w = tf32r(v.w);
        ((float4*)out)[i] = v;
    }
}

// ---------------------------------------------------------------------------
// Weight transpose (emits tf32-rounded values): out[c][r] = rnd(in[r][c])
// ---------------------------------------------------------------------------
__global__ __launch_bounds__(256) void transpose_kernel(
    const float* __restrict__ in, float* __restrict__ out,
    int rows, int cols, long zStride)
{
    __shared__ float tile[32][33];
    in  += (long)blockIdx.z * zStride;
    out += (long)blockIdx.z * zStride;
    const int c0 = blockIdx.x * 32;
    const int r0 = blockIdx.y * 32;
    const int tx = threadIdx.x & 31;
    const int ty = threadIdx.x >> 5;          // 0..7
#pragma unroll
    for (int j = 0; j < 32; j += 8)
        tile[ty + j][tx] = in[(long)(r0 + ty + j) * cols + c0 + tx];
    __syncthreads();
#pragma unroll
    for (int j = 0; j < 32; j += 8)
        out[(long)(c0 + ty + j) * rows + r0 + tx] = tf32r(tile[tx][ty + j]);
}

// ---------------------------------------------------------------------------
// tf32 mma.sync GEMM: C[M,N] = A[M,K] (row-major) x Bt[N,K] (K-major rows)
// CTA tile 128x128, BK=32, 8 warps (warp tile 64x32), 2-stage cp.async,
// register double-buffered fragments. Operands pre-rounded to tf32.
// ---------------------------------------------------------------------------
#define GEMM_SMEM_TOTAL (2 * 32768)

__global__ __launch_bounds__(256) void tf32_gemm(
    const float* __restrict__ A, const float* __restrict__ Bt,
    float* __restrict__ C, int K, int lda, int ldb, int ldc,
    long bStride, long cStride)
{
    extern __shared__ __align__(1024) char smem[];
    const int tid = threadIdx.x;
    const int wid = tid >> 5;
    const int lane = tid & 31;
    const int g = lane >> 2;        // group (row within fragment)
    const int t = lane & 3;         // thread-in-group (k within fragment)
    const int warp_m = wid >> 2;    // 0..1
    const int warp_n = wid & 3;     // 0..3

    Bt += (long)blockIdx.z * bStride;
    C  += (long)blockIdx.z * cStride;
    const int brow = blockIdx.y * 128;
    const int bcol = blockIdx.x * 128;

    const float* Ab = A + (long)brow * lda;
    const float* Bb = Bt + (long)bcol * ldb;

    // loader: 128 rows x 32 floats per matrix = 1024 16B chunks each
    const int lrow = tid >> 1;             // 0..127 (2 threads per row)
    const int lch4 = (tid & 1) << 2;       // chunk 0..3 or 4..7 start
    auto load_chunk = [&](int k0, int s) {
        char* sA = smem + s * 32768;
        char* sB = sA + 16384;
        const float* ga = Ab + (long)lrow * lda + k0 + (lch4 << 2);
        const float* gb = Bb + (long)lrow * ldb + k0 + (lch4 << 2);
#pragma unroll
        for (int c = 0; c < 4; c++) {
            const uint32_t off = SW128((uint32_t)((lrow << 7) + ((lch4 + c) << 4)));
            cp_async16(sA + off, ga + (c << 2));
            cp_async16(sB + off, gb + (c << 2));
        }
    };

    // fragment loader: 24 raw LDS.32, no cvt (operands pre-rounded)
    auto frag_load = [&](const char* sA, const char* sB, int ks,
                         uint32_t (&af)[4][4], uint32_t (&bf)[4][2]) {
        const int c0 = ((ks << 3) + t) << 2;
        const int c1 = c0 + 16;
#pragma unroll
        for (int nt = 0; nt < 4; nt++) {
            const int r = warp_n * 32 + nt * 8 + g;
            const uint32_t rb = (uint32_t)(r << 7);
            const uint32_t m = (uint32_t)((r & 7) << 4);
            bf[nt][0] = *(const uint32_t*)(sB + rb + (c0 ^ m));
            bf[nt][1] = *(const uint32_t*)(sB + rb + (c1 ^ m));
        }
#pragma unroll
        for (int mt = 0; mt < 4; mt++) {
            const int r0 = warp_m * 64 + mt * 16 + g;
            const int r1 = r0 + 8;
            const uint32_t b0 = (uint32_t)(r0 << 7), m0 = (uint32_t)((r0 & 7) << 4);
            const uint32_t b1 = (uint32_t)(r1 << 7), m1 = (uint32_t)((r1 & 7) << 4);
            af[mt][0] = *(const uint32_t*)(sA + b0 + (c0 ^ m0));
            af[mt][1] = *(const uint32_t*)(sA + b1 + (c0 ^ m1));
            af[mt][2] = *(const uint32_t*)(sA + b0 + (c1 ^ m0));
            af[mt][3] = *(const uint32_t*)(sA + b1 + (c1 ^ m1));
        }
    };

    float acc[4][4][4];
#pragma unroll
    for (int i = 0; i < 4; i++)
#pragma unroll
        for (int j = 0; j < 4; j++)
#pragma unroll
            for (int r = 0; r < 4; r++) acc[i][j][r] = 0.f;

    const int NCH = K >> 5;
    load_chunk(0, 0);
    CP_COMMIT();

    for (int i = 0; i < NCH; i++) {
        if (i + 1 < NCH) {
            load_chunk((i + 1) << 5, (i + 1) & 1);
            CP_COMMIT();
            CP_WAIT(1);
        } else {
            CP_WAIT(0);
        }
        __syncthreads();

        const char* sA = smem + (i & 1) * 32768;
        const char* sB = sA + 16384;

        uint32_t af[2][4][4];
        uint32_t bf[2][4][2];
        frag_load(sA, sB, 0, af[0], bf[0]);
#pragma unroll
        for (int ks = 0; ks < 4; ks++) {
            if (ks < 3) frag_load(sA, sB, ks + 1, af[(ks + 1) & 1], bf[(ks + 1) & 1]);
            const int cur = ks & 1;
#pragma unroll
            for (int mt = 0; mt < 4; mt++)
#pragma unroll
                for (int nt = 0; nt < 4; nt++)
                    mma_tf32(acc[mt][nt], af[cur][mt], bf[cur][nt]);
        }
        __syncthreads();
    }

    // epilogue: c0,c1 at (row, col+2t), c2,c3 at (row+8, col+2t)
#pragma unroll
    for (int mt = 0; mt < 4; mt++) {
        const int row = brow + warp_m * 64 + mt * 16 + g;
#pragma unroll
        for (int nt = 0; nt < 4; nt++) {
            const int col = bcol + warp_n * 32 + nt * 8 + 2 * t;
            float* Cp = C + (long)row * ldc + col;
            *(float2*)Cp = make_float2(acc[mt][nt][0], acc[mt][nt][1]);
            *(float2*)(Cp + 8 * ldc) = make_float2(acc[mt][nt][2], acc[mt][nt][3]);
        }
    }
}

// ---------------------------------------------------------------------------
// Router: per-token logits over 8 neurons for up to 3 routers, then softmax.
// ---------------------------------------------------------------------------
template <int DIM, int NR>
__global__ __launch_bounds__(256) void router_kernel(
    const float* __restrict__ x,
    const float* __restrict__ wr0, const float* __restrict__ wr1,
    const float* __restrict__ wr2,
    float* __restrict__ o0, float* __restrict__ o1, float* __restrict__ o2)
{
    __shared__ float xs[DIM];
    __shared__ float lg[NR][8];
    const long t = blockIdx.x;
    const float4* xrow = (const float4*)(x + t * DIM);
    for (int i = threadIdx.x; i < DIM / 4; i += 256)
        ((float4*)xs)[i] = xrow[i];
    __syncthreads();

    const int w = threadIdx.x >> 5;
    const int lane = threadIdx.x & 31;
    const float* wrs[3] = {wr0, wr1, wr2};
#pragma unroll
    for (int rt = 0; rt < NR; rt++) {
        const float4* wv4 = (const float4*)(wrs[rt] + w * DIM);
        float s = 0.f;
#pragma unroll
        for (int i = lane; i < DIM / 4; i += 32) {
            float4 a = ((const float4*)xs)[i];
            float4 b = wv4[i];
            s += a.x * b.x + a.y * b.y + a.z * b.z + a.w * b.w;
        }
#pragma unroll
        for (int off = 16; off; off >>= 1)
            s += __shfl_xor_sync(0xffffffffu, s, off);
        if (lane == 0) lg[rt][w] = s;
    }
    __syncthreads();

    if (threadIdx.x < NR) {
        const int rt = threadIdx.x;
        float mx = lg[rt][0];
#pragma unroll
        for (int n = 1; n < 8; n++) mx = fmaxf(mx, lg[rt][n]);
        float e[8];
        float sum = 0.f;
#pragma unroll
        for (int n = 0; n < 8; n++) { e[n] = __expf(lg[rt][n] - mx); sum += e[n]; }
        const float inv = 1.f / sum;
        float* o = (rt == 0 ? o0 : (rt == 1 ? o1 : o2)) + t * 8;
#pragma unroll
        for (int n = 0; n < 8; n++) o[n] = e[n] * inv;
    }
}

// ---------------------------------------------------------------------------
// q/k/v[t,r] = sum_n P[t, n*512 + r] * w{q,k,v}[t,n]
// ---------------------------------------------------------------------------
__global__ __launch_bounds__(128) void reduce_qkv(
    const float* __restrict__ P,
    const float* __restrict__ wq, const float* __restrict__ wk,
    const float* __restrict__ wv,
    float* __restrict__ q, float* __restrict__ k, float* __restrict__ v)
{
    const long t = blockIdx.x;
    __shared__ float sq[8], sk[8], sv[8];
    if (threadIdx.x < 8) {
        sq[threadIdx.x] = wq[t * 8 + threadIdx.x];
        sk[threadIdx.x] = wk[t * 8 + threadIdx.x];
        sv[threadIdx.x] = wv[t * 8 + threadIdx.x];
    }
    __syncthreads();
    const float* Pt = P + t * PCOLS;
    for (int r = threadIdx.x; r < Rz; r += 128) {
        float aq = 0.f, ak = 0.f, av = 0.f;
#pragma unroll
        for (int n = 0; n < 8; n++) {
            float p = Pt[n * Rz + r];
            aq += p * sq[n];
            ak += p * sk[n];
            av += p * sv[n];
        }
        q[t * Rz + r] = aq;
        k[t * Rz + r] = ak;
        v[t * Rz + r] = av;
    }
}

// ---------------------------------------------------------------------------
// Causal flash attention, fp32. float4 smem reads (crossbar fix).
// ---------------------------------------------------------------------------
__global__ __launch_bounds__(128) void attn_kernel(
    const float* __restrict__ q, const float* __restrict__ k,
    const float* __restrict__ v, float* __restrict__ out)
{
    const int KV = 32;
    __shared__ __align__(16) float Ks[KV][DHz];
    __shared__ __align__(16) float Vs[KV][DHz];

    const int bh = blockIdx.y;
    const int b = bh >> 3;
    const int h = bh & 7;
    const int qrow = blockIdx.x * 128 + threadIdx.x;

    const float* qp = q + ((long)b * Sz + qrow) * Rz + h * DHz;
    float qreg[DHz];
#pragma unroll
    for (int d = 0; d < DHz; d++) qreg[d] = qp[d];

    float acc[DHz];
#pragma unroll
    for (int d = 0; d < DHz; d++) acc[d] = 0.f;
    float m = -1e30f, l = 0.f;

    const float* kb = k + (long)b * Sz * Rz + h * DHz;
    const float* vb = v + (long)b * Sz * Rz + h * DHz;
    const int ntiles = (blockIdx.x * 128 + 127) / KV + 1;

    for (int tt = 0; tt < ntiles; tt++) {
        const int base = tt * KV;
        for (int i = threadIdx.x; i < KV * DHz / 4; i += 128) {
            int row = i >> 4;
            int col = (i & 15) << 2;
            *(float4*)&Ks[row][col] = *(const float4*)(kb + (long)(base + row) * Rz + col);
            *(float4*)&Vs[row][col] = *(const float4*)(vb + (long)(base + row) * Rz + col);
        }
        __syncthreads();

        if (base <= qrow) {
            float sc[KV];
            float tmax = -1e30f;
#pragma unroll
            for (int j = 0; j < KV; j++) {
                const float4* kr = (const float4*)Ks[j];
                float s = 0.f;
#pragma unroll
                for (int d4 = 0; d4 < DHz / 4; d4++) {
                    float4 kk = kr[d4];
                    s += qreg[4 * d4 + 0] * kk.x + qreg[4 * d4 + 1] * kk.y
                       + qreg[4 * d4 + 2] * kk.z + qreg[4 * d4 + 3] * kk.w;
                }
                s *= 0.125f;
                s = (base + j <= qrow) ? s : -1e30f;
                sc[j] = s;
                tmax = fmaxf(tmax, s);
            }
            const float mn = fmaxf(m, tmax);
            const float corr = __expf(m - mn);
            l *= corr;
#pragma unroll
            for (int d = 0; d < DHz; d++) acc[d] *= corr;
#pragma unroll
            for (int j = 0; j < KV; j++) {
                const float p = __expf(sc[j] - mn);
                l += p;
                const float4* vr = (const float4*)Vs[j];
#pragma unroll
                for (int d4 = 0; d4 < DHz / 4; d4++) {
                    float4 vv = vr[d4];
                    acc[4 * d4 + 0] += p * vv.x;
                    acc[4 * d4 + 1] += p * vv.y;
                    acc[4 * d4 + 2] += p * vv.z;
                    acc[4 * d4 + 3] += p * vv.w;
                }
            }
            m = mn;
        }
        __syncthreads();
    }

    const float inv = 1.f / l;
    float* op = out + ((long)b * Sz + qrow) * Rz + h * DHz;
#pragma unroll
    for (int d = 0; d < DHz; d++) op[d] = acc[d] * inv;
}

// ---------------------------------------------------------------------------
// A'[t, n*512 + r] = rnd(wo[t,n] * attn[t,r])  (pre-rounded for GEMM2)
// ---------------------------------------------------------------------------
__global__ __launch_bounds__(256) void build_expand_A(
    const float* __restrict__ attn, const float* __restrict__ wo,
    float* __restrict__ Aout)
{
    __shared__ float as_[Rz];
    __shared__ float ws[8];
    const long t = blockIdx.x;
    for (int i = threadIdx.x; i < Rz / 4; i += 256)
        ((float4*)as_)[i] = ((const float4*)(attn + t * Rz))[i];
    if (threadIdx.x < 8) ws[threadIdx.x] = wo[t * 8 + threadIdx.x];
    __syncthreads();
    for (int i = threadIdx.x; i < (8 * Rz / 4); i += 256) {
        int n = i >> 7;
        int r4 = i & 127;
        float4 a = ((float4*)as_)[r4];
        float wn = ws[n];
        ((float4*)(Aout + t * PCOLS + n * Rz))[r4] =
            make_float4(tf32r(a.x * wn), tf32r(a.y * wn),
                        tf32r(a.z * wn), tf32r(a.w * wn));
    }
}

// ---------------------------------------------------------------------------
extern "C" void kernel_launch(void* const* d_in, const int* in_sizes, int n_in,
                              void* d_out, int out_size)
{
    const float* x   = (const float*)d_in[0];
    // d_in[1] = mask: always causal tril -> applied analytically, not read
    const float* CN  = (const float*)d_in[2];  // [NC, D, R]
    const float* EN  = (const float*)d_in[3];  // [NE, R, D]
    const float* wrq = (const float*)d_in[4];
    const float* wrk = (const float*)d_in[5];
    const float* wrv = (const float*)d_in[6];
    const float* wro = (const float*)d_in[7];
    float* out = (float*)d_out;

    float *P, *Xr, *q, *k, *v, *attn, *wq, *wk, *wv, *wo, *CNt, *ENt;
    cudaGetSymbolAddress((void**)&P,    g_P);
    cudaGetSymbolAddress((void**)&Xr,   g_Xr);
    cudaGetSymbolAddress((void**)&q,    g_q);
    cudaGetSymbolAddress((void**)&k,    g_k);
    cudaGetSymbolAddress((void**)&v,    g_v);
    cudaGetSymbolAddress((void**)&attn, g_attn);
    cudaGetSymbolAddress((void**)&wq,   g_wq);
    cudaGetSymbolAddress((void**)&wk,   g_wk);
    cudaGetSymbolAddress((void**)&wv,   g_wv);
    cudaGetSymbolAddress((void**)&wo,   g_wo);
    cudaGetSymbolAddress((void**)&CNt,  g_CNt);
    cudaGetSymbolAddress((void**)&ENt,  g_ENt);

    cudaFuncSetAttribute(tf32_gemm, cudaFuncAttributeMaxDynamicSharedMemorySize,
                         GEMM_SMEM_TOTAL);

    // 0) pre-round operands: weights (transposed+rounded), x (rounded copy)
    transpose_kernel<<<dim3(Rz / 32, Dz / 32, NCz), 256>>>(
        CN, CNt, Dz, Rz, (long)Dz * Rz);
    transpose_kernel<<<dim3(Dz / 32, PCOLS / 32, 1), 256>>>(
        EN, ENt, PCOLS, Dz, 0);
    round_tf32<<<592, 256>>>(x, Xr, (long)Tz * Dz / 4);

    // 1) compress routers (q,k,v share one pass over x; fp32 x for accuracy)
    router_kernel<Dz, 3><<<Tz, 256>>>(x, wrq, wrk, wrv, wq, wk, wv);

    // 2) P = x @ compress_neurons  (mma.sync tf32, batched over NC=8)
    tf32_gemm<<<dim3(Rz / 128, Tz / 128, NCz), 256, GEMM_SMEM_TOTAL>>>(
        Xr, CNt, P, Dz, Dz, Dz, PCOLS, (long)Rz * Dz, (long)Rz);

    // 3) weighted reduce -> q,k,v
    reduce_qkv<<<Tz, 128>>>(P, wq, wk, wv, q, k, v);

    // 4) causal attention
    attn_kernel<<<dim3(Sz / 128, Bz * Hz), 128>>>(q, k, v, attn);

    // 5) expand router
    router_kernel<Rz, 1><<<Tz, 256>>>(attn, wro, nullptr, nullptr,
                                      wo, nullptr, nullptr);

    // 6) A' = rnd(wo (x) attn)   (reuses P)
    build_expand_A<<<Tz, 256>>>(attn, wo, P);

    // 7) out = A' @ expand_neurons  (mma.sync tf32)
    tf32_gemm<<<dim3(Dz / 128, Tz / 128, 1), 256, GEMM_SMEM_TOTAL>>>(
        P, ENt, out, PCOLS, PCOLS, PCOLS, Dz, 0, 0);
}

// round 7
// speedup vs baseline: 3.1705x; 2.6310x over previous
#include <cuda_runtime.h>
#include <cstdint>

// ---------------------------------------------------------------------------
// NeuronCircuit: compress (MoE-weighted proj) -> causal MHA -> expand
// B=4 S=2048 D=1024 R=512 H=8 NC=NE=8 DH=64
//
// Round 5 -> 6: fix misaligned ST.64 in attention output staging (odd 17-word
// row stride -> scalar stores). Everything else identical to round 5.
// ---------------------------------------------------------------------------

#define Bz 4
#define Sz 2048
#define Dz 1024
#define Rz 512
#define Hz 8
#define NCz 8
#define DHz 64
#define Tz (Bz * Sz)          // 8192 tokens
#define PCOLS (NCz * Rz)      // 4096

// Scratch (device globals: allocation-free rule)
__device__ float g_P[(size_t)Tz * PCOLS];   // 134 MB, reused as A' for expand
__device__ float g_Xr[(size_t)Tz * Dz];     // tf32-rounded x (32 MB)
__device__ float g_q[Tz * Rz];
__device__ float g_k[Tz * Rz];
__device__ float g_v[Tz * Rz];
__device__ float g_attn[Tz * Rz];
__device__ float g_wq[Tz * NCz];
__device__ float g_wk[Tz * NCz];
__device__ float g_wv[Tz * NCz];
__device__ float g_wo[Tz * NCz];
__device__ float g_CNt[(size_t)NCz * Rz * Dz];   // [NC][R][D]  (16 MB)
__device__ float g_ENt[(size_t)Dz * PCOLS];      // [D][NE*R]   (16 MB)

// ---------------------------------------------------------------------------
// Baseline-PTX helpers (valid on compute_103): cp.async + mma.sync tf32
// ---------------------------------------------------------------------------
#define SW128(off) ((off) ^ (((off) >> 3) & 0x70))

__device__ __forceinline__ void cp_async16(void* smem_dst, const void* gmem_src) {
    uint32_t d = (uint32_t)__cvta_generic_to_shared(smem_dst);
    asm volatile("cp.async.cg.shared.global [%0], [%1], 16;"
                 :: "r"(d), "l"(gmem_src) : "memory");
}
#define CP_COMMIT() asm volatile("cp.async.commit_group;" ::: "memory")
#define CP_WAIT(n)  asm volatile("cp.async.wait_group %0;" :: "n"(n) : "memory")

__device__ __forceinline__ float tf32r(float x) {
    uint32_t r;
    asm("cvt.rna.tf32.f32 %0, %1;" : "=r"(r) : "f"(x));
    return __uint_as_float(r);
}

__device__ __forceinline__ void mma_tf32(float* d, const uint32_t* a, const uint32_t* b) {
    asm volatile(
        "mma.sync.aligned.m16n8k8.row.col.f32.tf32.tf32.f32 "
        "{%0,%1,%2,%3}, {%4,%5,%6,%7}, {%8,%9}, {%0,%1,%2,%3};"
        : "+f"(d[0]), "+f"(d[1]), "+f"(d[2]), "+f"(d[3])
        : "r"(a[0]), "r"(a[1]), "r"(a[2]), "r"(a[3]), "r"(b[0]), "r"(b[1]));
}

// FFMA-only 2^y (y <= 0 after softmax-max subtraction), err ~2e-6
__device__ __forceinline__ float fexp2(float y) {
    y = fmaxf(y, -120.f);
    float tt = y + 12582912.f;                       // 1.5 * 2^23
    int i = __float_as_int(tt) - 0x4B400000;         // round(y)
    float f = y - (tt - 12582912.f);                 // frac in [-0.5, 0.5]
    float p =               1.3333558146428443e-3f;
    p = fmaf(p, f, 9.618129107628477e-3f);
    p = fmaf(p, f, 5.550410866482158e-2f);
    p = fmaf(p, f, 2.402265069591007e-1f);
    p = fmaf(p, f, 6.931471805599453e-1f);
    p = fmaf(p, f, 1.0f);
    return __int_as_float(__float_as_int(p) + (i << 23));
}

// ---------------------------------------------------------------------------
// Elementwise tf32 rounding (grid-stride, float4)
// ---------------------------------------------------------------------------
__global__ __launch_bounds__(256) void round_tf32(
    const float* __restrict__ in, float* __restrict__ out, long n4)
{
    for (long i = blockIdx.x * 256L + threadIdx.x; i < n4; i += gridDim.x * 256L) {
        float4 v = ((const float4*)in)[i];
        v.x = tf32r(v.x); v.y = tf32r(v.y); v.z = tf32r(v.z); v.w = tf32r(v.w);
        ((float4*)out)[i] = v;
    }
}

// ---------------------------------------------------------------------------
// Weight transpose (emits tf32-rounded values): out[c][r] = rnd(in[r][c])
// ---------------------------------------------------------------------------
__global__ __launch_bounds__(256) void transpose_kernel(
    const float* __restrict__ in, float* __restrict__ out,
    int rows, int cols, long zStride)
{
    __shared__ float tile[32][33];
    in  += (long)blockIdx.z * zStride;
    out += (long)blockIdx.z * zStride;
    const int c0 = blockIdx.x * 32;
    const int r0 = blockIdx.y * 32;
    const int tx = threadIdx.x & 31;
    const int ty = threadIdx.x >> 5;          // 0..7
#pragma unroll
    for (int j = 0; j < 32; j += 8)
        tile[ty + j][tx] = in[(long)(r0 + ty + j) * cols + c0 + tx];
    __syncthreads();
#pragma unroll
    for (int j = 0; j < 32; j += 8)
        out[(long)(c0 + ty + j) * rows + r0 + tx] = tf32r(tile[tx][ty + j]);
}

// ---------------------------------------------------------------------------
// tf32 mma.sync GEMM (unchanged)
// ---------------------------------------------------------------------------
#define GEMM_SMEM_TOTAL (2 * 32768)

__global__ __launch_bounds__(256) void tf32_gemm(
    const float* __restrict__ A, const float* __restrict__ Bt,
    float* __restrict__ C, int K, int lda, int ldb, int ldc,
    long bStride, long cStride)
{
    extern __shared__ __align__(1024) char smem[];
    const int tid = threadIdx.x;
    const int wid = tid >> 5;
    const int lane = tid & 31;
    const int g = lane >> 2;
    const int t = lane & 3;
    const int warp_m = wid >> 2;
    const int warp_n = wid & 3;

    Bt += (long)blockIdx.z * bStride;
    C  += (long)blockIdx.z * cStride;
    const int brow = blockIdx.y * 128;
    const int bcol = blockIdx.x * 128;

    const float* Ab = A + (long)brow * lda;
    const float* Bb = Bt + (long)bcol * ldb;

    const int lrow = tid >> 1;
    const int lch4 = (tid & 1) << 2;
    auto load_chunk = [&](int k0, int s) {
        char* sA = smem + s * 32768;
        char* sB = sA + 16384;
        const float* ga = Ab + (long)lrow * lda + k0 + (lch4 << 2);
        const float* gb = Bb + (long)lrow * ldb + k0 + (lch4 << 2);
#pragma unroll
        for (int c = 0; c < 4; c++) {
            const uint32_t off = SW128((uint32_t)((lrow << 7) + ((lch4 + c) << 4)));
            cp_async16(sA + off, ga + (c << 2));
            cp_async16(sB + off, gb + (c << 2));
        }
    };

    auto frag_load = [&](const char* sA, const char* sB, int ks,
                         uint32_t (&af)[4][4], uint32_t (&bf)[4][2]) {
        const int c0 = ((ks << 3) + t) << 2;
        const int c1 = c0 + 16;
#pragma unroll
        for (int nt = 0; nt < 4; nt++) {
            const int r = warp_n * 32 + nt * 8 + g;
            const uint32_t rb = (uint32_t)(r << 7);
            const uint32_t m = (uint32_t)((r & 7) << 4);
            bf[nt][0] = *(const uint32_t*)(sB + rb + (c0 ^ m));
            bf[nt][1] = *(const uint32_t*)(sB + rb + (c1 ^ m));
        }
#pragma unroll
        for (int mt = 0; mt < 4; mt++) {
            const int r0 = warp_m * 64 + mt * 16 + g;
            const int r1 = r0 + 8;
            const uint32_t b0 = (uint32_t)(r0 << 7), m0 = (uint32_t)((r0 & 7) << 4);
            const uint32_t b1 = (uint32_t)(r1 << 7), m1 = (uint32_t)((r1 & 7) << 4);
            af[mt][0] = *(const uint32_t*)(sA + b0 + (c0 ^ m0));
            af[mt][1] = *(const uint32_t*)(sA + b1 + (c0 ^ m1));
            af[mt][2] = *(const uint32_t*)(sA + b0 + (c1 ^ m0));
            af[mt][3] = *(const uint32_t*)(sA + b1 + (c1 ^ m1));
        }
    };

    float acc[4][4][4];
#pragma unroll
    for (int i = 0; i < 4; i++)
#pragma unroll
        for (int j = 0; j < 4; j++)
#pragma unroll
            for (int r = 0; r < 4; r++) acc[i][j][r] = 0.f;

    const int NCH = K >> 5;
    load_chunk(0, 0);
    CP_COMMIT();

    for (int i = 0; i < NCH; i++) {
        if (i + 1 < NCH) {
            load_chunk((i + 1) << 5, (i + 1) & 1);
            CP_COMMIT();
            CP_WAIT(1);
        } else {
            CP_WAIT(0);
        }
        __syncthreads();

        const char* sA = smem + (i & 1) * 32768;
        const char* sB = sA + 16384;

        uint32_t af[2][4][4];
        uint32_t bf[2][4][2];
        frag_load(sA, sB, 0, af[0], bf[0]);
#pragma unroll
        for (int ks = 0; ks < 4; ks++) {
            if (ks < 3) frag_load(sA, sB, ks + 1, af[(ks + 1) & 1], bf[(ks + 1) & 1]);
            const int cur = ks & 1;
#pragma unroll
            for (int mt = 0; mt < 4; mt++)
#pragma unroll
                for (int nt = 0; nt < 4; nt++)
                    mma_tf32(acc[mt][nt], af[cur][mt], bf[cur][nt]);
        }
        __syncthreads();
    }

#pragma unroll
    for (int mt = 0; mt < 4; mt++) {
        const int row = brow + warp_m * 64 + mt * 16 + g;
#pragma unroll
        for (int nt = 0; nt < 4; nt++) {
            const int col = bcol + warp_n * 32 + nt * 8 + 2 * t;
            float* Cp = C + (long)row * ldc + col;
            *(float2*)Cp = make_float2(acc[mt][nt][0], acc[mt][nt][1]);
            *(float2*)(Cp + 8 * ldc) = make_float2(acc[mt][nt][2], acc[mt][nt][3]);
        }
    }
}

// ---------------------------------------------------------------------------
// Router (unchanged)
// ---------------------------------------------------------------------------
template <int DIM, int NR>
__global__ __launch_bounds__(256) void router_kernel(
    const float* __restrict__ x,
    const float* __restrict__ wr0, const float* __restrict__ wr1,
    const float* __restrict__ wr2,
    float* __restrict__ o0, float* __restrict__ o1, float* __restrict__ o2)
{
    __shared__ float xs[DIM];
    __shared__ float lg[NR][8];
    const long t = blockIdx.x;
    const float4* xrow = (const float4*)(x + t * DIM);
    for (int i = threadIdx.x; i < DIM / 4; i += 256)
        ((float4*)xs)[i] = xrow[i];
    __syncthreads();

    const int w = threadIdx.x >> 5;
    const int lane = threadIdx.x & 31;
    const float* wrs[3] = {wr0, wr1, wr2};
#pragma unroll
    for (int rt = 0; rt < NR; rt++) {
        const float4* wv4 = (const float4*)(wrs[rt] + w * DIM);
        float s = 0.f;
#pragma unroll
        for (int i = lane; i < DIM / 4; i += 32) {
            float4 a = ((const float4*)xs)[i];
            float4 b = wv4[i];
            s += a.x * b.x + a.y * b.y + a.z * b.z + a.w * b.w;
        }
#pragma unroll
        for (int off = 16; off; off >>= 1)
            s += __shfl_xor_sync(0xffffffffu, s, off);
        if (lane == 0) lg[rt][w] = s;
    }
    __syncthreads();

    if (threadIdx.x < NR) {
        const int rt = threadIdx.x;
        float mx = lg[rt][0];
#pragma unroll
        for (int n = 1; n < 8; n++) mx = fmaxf(mx, lg[rt][n]);
        float e[8];
        float sum = 0.f;
#pragma unroll
        for (int n = 0; n < 8; n++) { e[n] = __expf(lg[rt][n] - mx); sum += e[n]; }
        const float inv = 1.f / sum;
        float* o = (rt == 0 ? o0 : (rt == 1 ? o1 : o2)) + t * 8;
#pragma unroll
        for (int n = 0; n < 8; n++) o[n] = e[n] * inv;
    }
}

// ---------------------------------------------------------------------------
// q/k/v reduce (unchanged)
// ---------------------------------------------------------------------------
__global__ __launch_bounds__(128) void reduce_qkv(
    const float* __restrict__ P,
    const float* __restrict__ wq, const float* __restrict__ wk,
    const float* __restrict__ wv,
    float* __restrict__ q, float* __restrict__ k, float* __restrict__ v)
{
    const long t = blockIdx.x;
    __shared__ float sq[8], sk[8], sv[8];
    if (threadIdx.x < 8) {
        sq[threadIdx.x] = wq[t * 8 + threadIdx.x];
        sk[threadIdx.x] = wk[t * 8 + threadIdx.x];
        sv[threadIdx.x] = wv[t * 8 + threadIdx.x];
    }
    __syncthreads();
    const float* Pt = P + t * PCOLS;
    for (int r = threadIdx.x; r < Rz; r += 128) {
        float aq = 0.f, ak = 0.f, av = 0.f;
#pragma unroll
        for (int n = 0; n < 8; n++) {
            float p = Pt[n * Rz + r];
            aq += p * sq[n];
            ak += p * sk[n];
            av += p * sv[n];
        }
        q[t * Rz + r] = aq;
        k[t * Rz + r] = ak;
        v[t * Rz + r] = av;
    }
}

// ---------------------------------------------------------------------------
// Tensor-core causal flash attention (tf32 mma.sync).
// Block: 64 q-rows, 4 warps (warp = 16 q-rows). KV tiles of 64.
// S = Q @ K^T via m16n8k8; PV computed transposed (no V/P transposes).
// exp via FFMA-only exp2 poly. Output staged via smem for coalesced STG.
// ---------------------------------------------------------------------------
#define PADT 68
#define ATTN_SMEM (3 * 64 * PADT * 4)
#define SCALE_L2E 0.1803368801111204f   // (1/sqrt(64)) * log2(e)

__global__ __launch_bounds__(128) void attn_tc_kernel(
    const float* __restrict__ q, const float* __restrict__ k,
    const float* __restrict__ v, float* __restrict__ out)
{
    extern __shared__ __align__(16) float sm[];
    float* Ks = sm;                    // [64][PADT]
    float* Vn = sm + 64 * PADT;        // [64][PADT]
    float* Ps = sm + 2 * 64 * PADT;    // [64][PADT], warp w owns rows w*16..+15

    const int bh = blockIdx.y;
    const int b = bh >> 3;
    const int h = bh & 7;
    const int qblk = gridDim.x - 1 - blockIdx.x;   // long blocks first
    const int qbase = qblk * 64;
    const int tid = threadIdx.x;
    const int w = tid >> 5;
    const int lane = tid & 31;
    const int g = lane >> 2;
    const int t = lane & 3;

    // Q fragments (tf32), rows w*16+g / +8, k = 8*ks + t / t+4
    const float* qb = q + ((long)b * Sz + qbase + w * 16) * Rz + h * DHz;
    uint32_t qf[8][4];
#pragma unroll
    for (int ks = 0; ks < 8; ks++) {
        qf[ks][0] = __float_as_uint(tf32r(qb[(long)g * Rz + 8 * ks + t]));
        qf[ks][1] = __float_as_uint(tf32r(qb[(long)(g + 8) * Rz + 8 * ks + t]));
        qf[ks][2] = __float_as_uint(tf32r(qb[(long)g * Rz + 8 * ks + t + 4]));
        qf[ks][3] = __float_as_uint(tf32r(qb[(long)(g + 8) * Rz + 8 * ks + t + 4]));
    }

    float Oa[4][2][4];                  // [d-mtile][q-nfrag][regs], transposed
#pragma unroll
    for (int a = 0; a < 4; a++)
#pragma unroll
        for (int bb = 0; bb < 2; bb++)
#pragma unroll
            for (int c = 0; c < 4; c++) Oa[a][bb][c] = 0.f;
    float m_lo = -1e30f, m_hi = -1e30f, l_lo = 0.f, l_hi = 0.f;

    const float* kb = k + (long)b * Sz * Rz + h * DHz;
    const float* vb = v + (long)b * Sz * Rz + h * DHz;
    const int ntiles = qblk + 1;

    for (int tt = 0; tt < ntiles; tt++) {
        const int kvb = tt * 64;
        __syncthreads();
        // cooperative K/V tile load, tf32-converted
#pragma unroll
        for (int i = tid; i < 1024; i += 128) {
            const int row = i >> 4;
            const int col = (i & 15) << 2;
            float4 kk = *(const float4*)(kb + (long)(kvb + row) * Rz + col);
            float4 vv = *(const float4*)(vb + (long)(kvb + row) * Rz + col);
            float* kd = Ks + row * PADT + col;
            float* vd = Vn + row * PADT + col;
            kd[0] = tf32r(kk.x); kd[1] = tf32r(kk.y); kd[2] = tf32r(kk.z); kd[3] = tf32r(kk.w);
            vd[0] = tf32r(vv.x); vd[1] = tf32r(vv.y); vd[2] = tf32r(vv.z); vd[3] = tf32r(vv.w);
        }
        __syncthreads();

        // S = Q @ K^T : warp computes 16 x 64
        float S[8][4];
#pragma unroll
        for (int nf = 0; nf < 8; nf++)
#pragma unroll
            for (int c = 0; c < 4; c++) S[nf][c] = 0.f;
#pragma unroll
        for (int ks = 0; ks < 8; ks++) {
            const int c0 = 8 * ks + t, c1 = c0 + 4;
#pragma unroll
            for (int nf = 0; nf < 8; nf++) {
                uint32_t bf[2];
                bf[0] = __float_as_uint(Ks[(nf * 8 + g) * PADT + c0]);
                bf[1] = __float_as_uint(Ks[(nf * 8 + g) * PADT + c1]);
                mma_tf32(S[nf], qf[ks], bf);
            }
        }

        // causal mask on the diagonal tile
        if (tt == qblk) {
            const int rl = w * 16 + g, rh = rl + 8;
#pragma unroll
            for (int nf = 0; nf < 8; nf++) {
                const int c0 = nf * 8 + 2 * t;
                if (c0 > rl)     S[nf][0] = -1e30f;
                if (c0 + 1 > rl) S[nf][1] = -1e30f;
                if (c0 > rh)     S[nf][2] = -1e30f;
                if (c0 + 1 > rh) S[nf][3] = -1e30f;
            }
        }

        // online softmax (raw-score max; scale folded into exp2)
        float mx_lo = -1e30f, mx_hi = -1e30f;
#pragma unroll
        for (int nf = 0; nf < 8; nf++) {
            mx_lo = fmaxf(mx_lo, fmaxf(S[nf][0], S[nf][1]));
            mx_hi = fmaxf(mx_hi, fmaxf(S[nf][2], S[nf][3]));
        }
        mx_lo = fmaxf(mx_lo, __shfl_xor_sync(0xffffffffu, mx_lo, 1));
        mx_lo = fmaxf(mx_lo, __shfl_xor_sync(0xffffffffu, mx_lo, 2));
        mx_hi = fmaxf(mx_hi, __shfl_xor_sync(0xffffffffu, mx_hi, 1));
        mx_hi = fmaxf(mx_hi, __shfl_xor_sync(0xffffffffu, mx_hi, 2));

        const float mn_lo = fmaxf(m_lo, mx_lo);
        const float mn_hi = fmaxf(m_hi, mx_hi);
        const float corr_lo = fexp2((m_lo - mn_lo) * SCALE_L2E);
        const float corr_hi = fexp2((m_hi - mn_hi) * SCALE_L2E);
        m_lo = mn_lo; m_hi = mn_hi;
        l_lo *= corr_lo; l_hi *= corr_hi;

        float psum_lo = 0.f, psum_hi = 0.f;
        float* pw = Ps + (w * 16) * PADT;
#pragma unroll
        for (int nf = 0; nf < 8; nf++) {
            const int c0 = nf * 8 + 2 * t;
            float p0 = fexp2((S[nf][0] - mn_lo) * SCALE_L2E);
            float p1 = fexp2((S[nf][1] - mn_lo) * SCALE_L2E);
            float p2 = fexp2((S[nf][2] - mn_hi) * SCALE_L2E);
            float p3 = fexp2((S[nf][3] - mn_hi) * SCALE_L2E);
            psum_lo += p0 + p1;
            psum_hi += p2 + p3;
            *(float2*)(pw + g * PADT + c0) = make_float2(tf32r(p0), tf32r(p1));
            *(float2*)(pw + (g + 8) * PADT + c0) = make_float2(tf32r(p2), tf32r(p3));
        }
        psum_lo += __shfl_xor_sync(0xffffffffu, psum_lo, 1);
        psum_lo += __shfl_xor_sync(0xffffffffu, psum_lo, 2);
        psum_hi += __shfl_xor_sync(0xffffffffu, psum_hi, 1);
        psum_hi += __shfl_xor_sync(0xffffffffu, psum_hi, 2);
        l_lo += psum_lo; l_hi += psum_hi;

        // rescale O' by per-q-column corr (q col = nf2*8 + 2t / +1)
        {
            const float cA  = __shfl_sync(0xffffffffu, corr_lo, 8 * t);
            const float cA1 = __shfl_sync(0xffffffffu, corr_lo, 8 * t + 4);
            const float cB  = __shfl_sync(0xffffffffu, corr_hi, 8 * t);
            const float cB1 = __shfl_sync(0xffffffffu, corr_hi, 8 * t + 4);
#pragma unroll
            for (int mt = 0; mt < 4; mt++) {
                Oa[mt][0][0] *= cA;  Oa[mt][0][1] *= cA1;
                Oa[mt][0][2] *= cA;  Oa[mt][0][3] *= cA1;
                Oa[mt][1][0] *= cB;  Oa[mt][1][1] *= cB1;
                Oa[mt][1][2] *= cB;  Oa[mt][1][3] *= cB1;
            }
        }
        __syncwarp();

        // O' += V^T-as-A @ P-as-B : per warp 64d x 16q
#pragma unroll
        for (int ks = 0; ks < 8; ks++) {
            const int k0 = 8 * ks + t, k1 = k0 + 4;
            uint32_t bfr[2][2];
#pragma unroll
            for (int nf2 = 0; nf2 < 2; nf2++) {
                bfr[nf2][0] = __float_as_uint(pw[(nf2 * 8 + g) * PADT + k0]);
                bfr[nf2][1] = __float_as_uint(pw[(nf2 * 8 + g) * PADT + k1]);
            }
#pragma unroll
            for (int mt = 0; mt < 4; mt++) {
                uint32_t af[4];
                af[0] = __float_as_uint(Vn[k0 * PADT + mt * 16 + g]);
                af[1] = __float_as_uint(Vn[k0 * PADT + mt * 16 + g + 8]);
                af[2] = __float_as_uint(Vn[k1 * PADT + mt * 16 + g]);
                af[3] = __float_as_uint(Vn[k1 * PADT + mt * 16 + g + 8]);
                mma_tf32(Oa[mt][0], af, bfr[0]);
                mma_tf32(Oa[mt][1], af, bfr[1]);
            }
        }
        __syncwarp();
    }

    // normalize by 1/l per q column
    const float il_lo = 1.f / l_lo;
    const float il_hi = 1.f / l_hi;
    {
        const float iA  = __shfl_sync(0xffffffffu, il_lo, 8 * t);
        const float iA1 = __shfl_sync(0xffffffffu, il_lo, 8 * t + 4);
        const float iB  = __shfl_sync(0xffffffffu, il_hi, 8 * t);
        const float iB1 = __shfl_sync(0xffffffffu, il_hi, 8 * t + 4);
#pragma unroll
        for (int mt = 0; mt < 4; mt++) {
            Oa[mt][0][0] *= iA;  Oa[mt][0][1] *= iA1;
            Oa[mt][0][2] *= iA;  Oa[mt][0][3] *= iA1;
            Oa[mt][1][0] *= iB;  Oa[mt][1][1] *= iB1;
            Oa[mt][1][2] *= iB;  Oa[mt][1][3] *= iB1;
        }
    }

    // stage O' -> warp's smem region as [d][17-padded q] (SCALAR stores:
    // 17-word row stride makes odd rows only 4B-aligned -> no ST.64 here)
    float* osm = Ps + (w * 16) * PADT;   // 1088 floats, need 64*17=1086
    __syncwarp();
#pragma unroll
    for (int mt = 0; mt < 4; mt++) {
#pragma unroll
        for (int nf2 = 0; nf2 < 2; nf2++) {
            const int qc = nf2 * 8 + 2 * t;
            osm[(mt * 16 + g) * 17 + qc]         = Oa[mt][nf2][0];
            osm[(mt * 16 + g) * 17 + qc + 1]     = Oa[mt][nf2][1];
            osm[(mt * 16 + g + 8) * 17 + qc]     = Oa[mt][nf2][2];
            osm[(mt * 16 + g + 8) * 17 + qc + 1] = Oa[mt][nf2][3];
        }
    }
    __syncwarp();
    float* ob = out + ((long)b * Sz + qbase + w * 16) * Rz + h * DHz;
#pragma unroll
    for (int it = 0; it < 8; it++) {
        const int qr = it * 2 + (lane >> 4);
        const int d4 = (lane & 15) << 2;
        float4 vv;
        vv.x = osm[(d4 + 0) * 17 + qr];
        vv.y = osm[(d4 + 1) * 17 + qr];
        vv.z = osm[(d4 + 2) * 17 + qr];
        vv.w = osm[(d4 + 3) * 17 + qr];
        *(float4*)(ob + (long)qr * Rz + d4) = vv;
    }
}

// ---------------------------------------------------------------------------
// A'[t, n*512 + r] = rnd(wo[t,n] * attn[t,r])  (pre-rounded for GEMM2)
// ---------------------------------------------------------------------------
__global__ __launch_bounds__(256) void build_expand_A(
    const float* __restrict__ attn, const float* __restrict__ wo,
    float* __restrict__ Aout)
{
    __shared__ float as_[Rz];
    __shared__ float ws[8];
    const long t = blockIdx.x;
    for (int i = threadIdx.x; i < Rz / 4; i += 256)
        ((float4*)as_)[i] = ((const float4*)(attn + t * Rz))[i];
    if (threadIdx.x < 8) ws[threadIdx.x] = wo[t * 8 + threadIdx.x];
    __syncthreads();
    for (int i = threadIdx.x; i < (8 * Rz / 4); i += 256) {
        int n = i >> 7;
        int r4 = i & 127;
        float4 a = ((float4*)as_)[r4];
        float wn = ws[n];
        ((float4*)(Aout + t * PCOLS + n * Rz))[r4] =
            make_float4(tf32r(a.x * wn), tf32r(a.y * wn),
                        tf32r(a.z * wn), tf32r(a.w * wn));
    }
}

// ---------------------------------------------------------------------------
extern "C" void kernel_launch(void* const* d_in, const int* in_sizes, int n_in,
                              void* d_out, int out_size)
{
    const float* x   = (const float*)d_in[0];
    // d_in[1] = mask: always causal tril -> applied analytically, not read
    const float* CN  = (const float*)d_in[2];  // [NC, D, R]
    const float* EN  = (const float*)d_in[3];  // [NE, R, D]
    const float* wrq = (const float*)d_in[4];
    const float* wrk = (const float*)d_in[5];
    const float* wrv = (const float*)d_in[6];
    const float* wro = (const float*)d_in[7];
    float* out = (float*)d_out;

    float *P, *Xr, *q, *k, *v, *attn, *wq, *wk, *wv, *wo, *CNt, *ENt;
    cudaGetSymbolAddress((void**)&P,    g_P);
    cudaGetSymbolAddress((void**)&Xr,   g_Xr);
    cudaGetSymbolAddress((void**)&q,    g_q);
    cudaGetSymbolAddress((void**)&k,    g_k);
    cudaGetSymbolAddress((void**)&v,    g_v);
    cudaGetSymbolAddress((void**)&attn, g_attn);
    cudaGetSymbolAddress((void**)&wq,   g_wq);
    cudaGetSymbolAddress((void**)&wk,   g_wk);
    cudaGetSymbolAddress((void**)&wv,   g_wv);
    cudaGetSymbolAddress((void**)&wo,   g_wo);
    cudaGetSymbolAddress((void**)&CNt,  g_CNt);
    cudaGetSymbolAddress((void**)&ENt,  g_ENt);

    cudaFuncSetAttribute(tf32_gemm, cudaFuncAttributeMaxDynamicSharedMemorySize,
                         GEMM_SMEM_TOTAL);
    cudaFuncSetAttribute(attn_tc_kernel, cudaFuncAttributeMaxDynamicSharedMemorySize,
                         ATTN_SMEM);

    // 0) pre-round operands
    transpose_kernel<<<dim3(Rz / 32, Dz / 32, NCz), 256>>>(
        CN, CNt, Dz, Rz, (long)Dz * Rz);
    transpose_kernel<<<dim3(Dz / 32, PCOLS / 32, 1), 256>>>(
        EN, ENt, PCOLS, Dz, 0);
    round_tf32<<<592, 256>>>(x, Xr, (long)Tz * Dz / 4);

    // 1) compress routers
    router_kernel<Dz, 3><<<Tz, 256>>>(x, wrq, wrk, wrv, wq, wk, wv);

    // 2) P = x @ compress_neurons
    tf32_gemm<<<dim3(Rz / 128, Tz / 128, NCz), 256, GEMM_SMEM_TOTAL>>>(
        Xr, CNt, P, Dz, Dz, Dz, PCOLS, (long)Rz * Dz, (long)Rz);

    // 3) weighted reduce -> q,k,v
    reduce_qkv<<<Tz, 128>>>(P, wq, wk, wv, q, k, v);

    // 4) causal attention (tensor cores)
    attn_tc_kernel<<<dim3(Sz / 64, Bz * Hz), 128, ATTN_SMEM>>>(q, k, v, attn);

    // 5) expand router
    router_kernel<Rz, 1><<<Tz, 256>>>(attn, wro, nullptr, nullptr,
                                      wo, nullptr, nullptr);

    // 6) A' = rnd(wo (x) attn)
    build_expand_A<<<Tz, 256>>>(attn, wo, P);

    // 7) out = A' @ expand_neurons
    tf32_gemm<<<dim3(Dz / 128, Tz / 128, 1), 256, GEMM_SMEM_TOTAL>>>(
        P, ENt, out, PCOLS, PCOLS, PCOLS, Dz, 0, 0);
}